// round 16
// baseline (speedup 1.0000x reference)
#include <cuda_runtime.h>
#include <cuda_bf16.h>
#include <math.h>

#define BATCH 1024
#define SEQ   250
#define EMB   100
#define VOCAB 50001
#define UNITS 128
#define GATES 512   // 4*UNITS, gate order i,f,g,o
#define DENSE 32

// Pre-converted operands (one-time kernels)
__device__ unsigned short g_WxT[GATES * 120];          // [n][k] bf16, k padded 120
__device__ unsigned short g_embh[(size_t)VOCAB * EMB]; // bf16 emb

__device__ __forceinline__ float bf2f(unsigned short v) {
    return __uint_as_float(((unsigned int)v) << 16);
}

// ---- mma.sync bf16 helpers (validated R12-R15) -----------------------------
__device__ __forceinline__ void ldsm_x4(unsigned& r0, unsigned& r1,
                                        unsigned& r2, unsigned& r3, unsigned addr) {
    asm volatile("ldmatrix.sync.aligned.m8n8.x4.shared.b16 {%0,%1,%2,%3}, [%4];"
                 : "=r"(r0), "=r"(r1), "=r"(r2), "=r"(r3) : "r"(addr));
}
__device__ __forceinline__ void ldsm_x2(unsigned& r0, unsigned& r1, unsigned addr) {
    asm volatile("ldmatrix.sync.aligned.m8n8.x2.shared.b16 {%0,%1}, [%2];"
                 : "=r"(r0), "=r"(r1) : "r"(addr));
}
__device__ __forceinline__ void mma16816(float* d,
                                         unsigned a0, unsigned a1, unsigned a2, unsigned a3,
                                         unsigned b0, unsigned b1) {
    asm volatile("mma.sync.aligned.m16n8k16.row.col.f32.bf16.bf16.f32 "
                 "{%0,%1,%2,%3}, {%4,%5,%6,%7}, {%8,%9}, {%0,%1,%2,%3};"
                 : "+f"(d[0]), "+f"(d[1]), "+f"(d[2]), "+f"(d[3])
                 : "r"(a0), "r"(a1), "r"(a2), "r"(a3), "r"(b0), "r"(b1));
}

// ---------------------------------------------------------------------------
// K0a: Wx -> bf16 transposed [n][k], k padded to 120 with zeros
// ---------------------------------------------------------------------------
__global__ void k0_wx(const float* __restrict__ Wx)
{
    int n = blockIdx.x;
    for (int k = threadIdx.x; k < 120; k += 128)
        g_WxT[n * 120 + k] = (k < EMB)
            ? (unsigned short)__bfloat16_as_ushort(__float2bfloat16(Wx[(size_t)k * GATES + n]))
            : (unsigned short)0;
}
// K0b: emb -> bf16
__global__ void k0_emb(const float* __restrict__ emb)
{
    for (size_t i = blockIdx.x * blockDim.x + threadIdx.x;
         i < (size_t)VOCAB * EMB; i += (size_t)gridDim.x * blockDim.x)
        g_embh[i] = (unsigned short)__bfloat16_as_ushort(__float2bfloat16(emb[i]));
}

// ---------------------------------------------------------------------------
// K2 (v10): FUSED embedding + input projection + LSTM recurrence + head.
//   128 CTAs x 8 batch rows, 512 threads = 16 warps, gate-aligned columns.
//   Per step t:
//     d = bias (regs)
//     d += x_t[16 pad][112] @ Wx      (A from xs[cur], B frags ldsm'd from
//                                      smem-resident wxs each step: 28 mma)
//     d += h[16 pad][128] @ Wh        (B register-resident: 32 mma)
//     gates in registers -> c, h -> hs[nxt]
//     (emb rows for t+1 gathered from L2-resident g_embh during the step,
//      STS'd into xs[nxt] at step bottom; token ids pre-staged in smem)
//   g_xz and the K1 kernel are GONE: no 524MB DRAM round-trip.
// ---------------------------------------------------------------------------
#define K2_THREADS 512
#define HS_STR   136
#define XS_STR   120
#define HSBUF_BYTES (16 * HS_STR * 2)                  // 4352
#define XSBUF_BYTES (16 * XS_STR * 2)                  // 3840
#define WXS_BYTES   (GATES * XS_STR * 2)               // 122880
#define HS_OFF   WXS_BYTES                             // 122880
#define XS_OFF   (HS_OFF + 2 * HSBUF_BYTES)            // 131584
#define TKS_OFF  (XS_OFF + 2 * XSBUF_BYTES)            // 139264
#define SM_TOTAL (TKS_OFF + 8 * SEQ * 4)               // 147264

__device__ __forceinline__ float tanh_fast(float x) {
    float r;
    asm("tanh.approx.f32 %0, %1;" : "=f"(r) : "f"(x));
    return r;
}
__device__ __forceinline__ float sigm_fast(float x) {
    return fmaf(0.5f, tanh_fast(0.5f * x), 0.5f);
}

__global__ __launch_bounds__(K2_THREADS, 1) void k2_fused(
    const int* __restrict__ tokens,
    const float* __restrict__ Wh, const float* __restrict__ lb,
    const float* __restrict__ W1, const float* __restrict__ b1,
    const float* __restrict__ W2, const float* __restrict__ b2,
    float* __restrict__ out)
{
    extern __shared__ __align__(16) unsigned char sm[];
    unsigned short* wxs = (unsigned short*)sm;                       // [512][120]
    unsigned short (*hs)[HS_STR] = (unsigned short (*)[HS_STR])(sm + HS_OFF);
    unsigned short (*xs)[XS_STR] = (unsigned short (*)[XS_STR])(sm + XS_OFF);
    int*   tks = (int*)(sm + TKS_OFF);                               // [8][250]
    float (*d1s)[DENSE] = (float (*)[DENSE])(sm + TKS_OFF);          // post-loop overlay
    unsigned short (*BsT)[HS_STR] = (unsigned short (*)[HS_STR])sm;  // setup overlay

    const int tid  = threadIdx.x;
    const int warp = tid >> 5;
    const int lane = tid & 31;
    const int b0   = blockIdx.x * 8;
    const int frow = lane >> 2;

    // ---- one-time: register-resident Wh B fragments, gate-aligned ----
    unsigned breg[8][4][2];
    #pragma unroll 1
    for (int p = 0; p < 4; p++) {
        for (int idx = tid; idx < 128 * 128; idx += K2_THREADS) {
            int n = idx & 127, k = idx >> 7;
            BsT[n][k] = (unsigned short)__bfloat16_as_ushort(
                __float2bfloat16(Wh[(size_t)k * GATES + p * 128 + n]));
        }
        __syncthreads();
        {
            unsigned b_base = (unsigned)__cvta_generic_to_shared(
                &BsT[warp * 8 + (lane & 7)][0]) + (((lane >> 3) & 1) * 8) * 2;
            #pragma unroll
            for (int kk = 0; kk < 8; kk++)
                ldsm_x2(breg[kk][p][0], breg[kk][p][1], b_base + kk * 32);
        }
        __syncthreads();
    }

    // ---- one-time: fill wxs from pre-transposed g_WxT (15 uint4 per row) ----
    for (int idx = tid; idx < GATES * 15; idx += K2_THREADS) {
        int n = idx / 15, q = idx - n * 15;
        *(uint4*)&wxs[n * XS_STR + q * 8] =
            *(const uint4*)&g_WxT[(size_t)n * XS_STR + q * 8];
    }
    // ---- one-time: stage this CTA's token rows (coalesced per row) ----
    for (int idx = tid; idx < 8 * SEQ; idx += K2_THREADS) {
        int r = idx / SEQ, t = idx - r * SEQ;
        tks[idx] = tokens[(size_t)(b0 + r) * SEQ + t];
    }
    // ---- zero hs (both buffers) and xs (both buffers) ----
    for (int i = tid; i < 2 * 16 * HS_STR; i += K2_THREADS)
        ((unsigned short*)(sm + HS_OFF))[i] = 0;
    for (int i = tid; i < 2 * 16 * XS_STR; i += K2_THREADS)
        ((unsigned short*)(sm + XS_OFF))[i] = 0;
    __syncthreads();

    // ---- initial gather: emb rows for t=0 into xs buffer 0 ----
    const int gr = tid / 25, gq = tid - 25 * (tid / 25);   // valid for tid<200
    if (tid < 200) {
        int tok = tks[gr * SEQ];
        *(uint2*)&xs[gr][gq * 4] = *(const uint2*)&g_embh[(size_t)tok * EMB + gq * 4];
    }
    __syncthreads();

    // ---- per-thread constants ----
    const int u0 = warp * 8 + (lane & 3) * 2;
    float2 bj[4];
    #pragma unroll
    for (int j = 0; j < 4; j++) bj[j] = *(const float2*)&lb[j * 128 + u0];

    unsigned a_hs = (unsigned)__cvta_generic_to_shared(
        &hs[lane & 15][(lane >> 4) * 8]);
    unsigned a_xs = (unsigned)__cvta_generic_to_shared(
        &xs[lane & 15][(lane >> 4) * 8]);
    unsigned bwx[4];
    #pragma unroll
    for (int j = 0; j < 4; j++)
        bwx[j] = (unsigned)__cvta_generic_to_shared(
            &wxs[(j * 128 + warp * 8 + (lane & 7)) * XS_STR + ((lane >> 3) & 1) * 8]);

    float c[2] = {0.0f, 0.0f};
    int cur = 0;
    for (int t = 0; t < SEQ; t++) {
        // seed accumulators from bias (rows 8-15 are dead)
        float d[4][4];
        #pragma unroll
        for (int j = 0; j < 4; j++) {
            d[j][0] = bj[j].x; d[j][1] = bj[j].y;
            d[j][2] = 0.0f;    d[j][3] = 0.0f;
        }

        // prefetch emb rows for t+1 (L2-resident table; STS at step bottom)
        uint2 gv;
        const bool dog = (tid < 200) && (t + 1 < SEQ);
        if (dog) {
            int tok = tks[gr * SEQ + t + 1];
            gv = *(const uint2*)&g_embh[(size_t)tok * EMB + gq * 4];
        }

        // d += x_t @ Wx  (A from xs[cur], B frags from smem-resident wxs)
        {
            unsigned ax = a_xs + cur * XSBUF_BYTES;
            #pragma unroll
            for (int kk = 0; kk < 7; kk++) {
                unsigned a0, a1, a2, a3;
                ldsm_x4(a0, a1, a2, a3, ax + kk * 32);
                #pragma unroll
                for (int j = 0; j < 4; j++) {
                    unsigned w0, w1;
                    ldsm_x2(w0, w1, bwx[j] + kk * 32);
                    mma16816(d[j], a0, a1, a2, a3, w0, w1);
                }
            }
        }
        // d += h @ Wh  (B register-resident)
        {
            unsigned ah = a_hs + cur * HSBUF_BYTES;
            #pragma unroll
            for (int kk = 0; kk < 8; kk++) {
                unsigned a0, a1, a2, a3;
                ldsm_x4(a0, a1, a2, a3, ah + kk * 32);
                #pragma unroll
                for (int j = 0; j < 4; j++)
                    mma16816(d[j], a0, a1, a2, a3, breg[kk][j][0], breg[kk][j][1]);
            }
        }

        // land the prefetched emb rows into xs[nxt]
        if (dog)
            *(uint2*)&xs[(cur ^ 1) * 16 + gr][gq * 4] = gv;

        // gate math in registers: d[0..3][h] = i,f,g,o of (frow, u0+h)
        float hv[2];
        #pragma unroll
        for (int h = 0; h < 2; h++) {
            float ig = sigm_fast(d[0][h]);
            float fg = sigm_fast(d[1][h]);
            float gg = tanh_fast(d[2][h]);
            float og = sigm_fast(d[3][h]);
            float cc = fg * c[h] + ig * gg;
            c[h] = cc;
            hv[h] = og * tanh_fast(cc);
        }
        *(__nv_bfloat162*)&hs[(cur ^ 1) * 16 + frow][u0] =
            __floats2bfloat162_rn(hv[0], hv[1]);
        __syncthreads();
        cur ^= 1;
    }

    // ---- dense head: relu(h @ W1 + b1) @ W2 + b2, softmax ----
    const unsigned short (*hf)[HS_STR] = &hs[cur * 16];
    if (tid < 256) {
        int r = tid >> 5;
        int j = tid & 31;
        float a = b1[j];
        #pragma unroll 8
        for (int k = 0; k < UNITS; k++)
            a += bf2f(hf[r][k]) * W1[k * DENSE + j];
        d1s[r][j] = fmaxf(a, 0.0f);
    }
    __syncthreads();
    if (tid < 8) {
        float l0 = b2[0], l1 = b2[1];
        #pragma unroll
        for (int j = 0; j < DENSE; j++) {
            float d = d1s[tid][j];
            l0 += d * W2[j * 2 + 0];
            l1 += d * W2[j * 2 + 1];
        }
        float m  = fmaxf(l0, l1);
        float e0 = __expf(l0 - m), e1 = __expf(l1 - m);
        float s  = __fdividef(1.0f, e0 + e1);
        out[(b0 + tid) * 2 + 0] = e0 * s;
        out[(b0 + tid) * 2 + 1] = e1 * s;
    }
}

// ---------------------------------------------------------------------------
extern "C" void kernel_launch(void* const* d_in, const int* in_sizes, int n_in,
                              void* d_out, int out_size)
{
    const int*   tokens = (const int*)  d_in[0];
    const float* emb    = (const float*)d_in[1];
    const float* Wx     = (const float*)d_in[2];
    const float* Wh     = (const float*)d_in[3];
    const float* lb     = (const float*)d_in[4];
    const float* W1     = (const float*)d_in[5];
    const float* b1     = (const float*)d_in[6];
    const float* W2     = (const float*)d_in[7];
    const float* b2     = (const float*)d_in[8];
    float* out = (float*)d_out;

    cudaFuncSetAttribute(k2_fused,
                         cudaFuncAttributeMaxDynamicSharedMemorySize, SM_TOTAL);

    k0_wx<<<GATES, 128>>>(Wx);
    k0_emb<<<2048, 256>>>(emb);
    k2_fused<<<BATCH / 8, K2_THREADS, SM_TOTAL>>>(tokens, Wh, lb,
                                                  W1, b1, W2, b2, out);
}

// round 17
// speedup vs baseline: 1.1189x; 1.1189x over previous
#include <cuda_runtime.h>
#include <cuda_bf16.h>
#include <math.h>

#define BATCH 1024
#define SEQ   250
#define EMB   100
#define VOCAB 50001
#define UNITS 128
#define GATES 512   // 4*UNITS, gate order i,f,g,o
#define DENSE 32

// Scratch: xz = emb[tokens] @ Wx + b, layout [t][b][512], bf16 (262 MB)
__device__ unsigned short g_xz[(size_t)SEQ * BATCH * GATES];
// Pre-converted operands (one-time kernels)
__device__ unsigned short g_WxT[GATES * 120];          // [n][k] bf16, k padded 120
__device__ unsigned short g_embh[(size_t)VOCAB * EMB]; // bf16 emb

__device__ __forceinline__ float bf2f(unsigned short v) {
    return __uint_as_float(((unsigned int)v) << 16);
}

// ---- mma.sync bf16 helpers (validated R12-R15) -----------------------------
__device__ __forceinline__ void ldsm_x4(unsigned& r0, unsigned& r1,
                                        unsigned& r2, unsigned& r3, unsigned addr) {
    asm volatile("ldmatrix.sync.aligned.m8n8.x4.shared.b16 {%0,%1,%2,%3}, [%4];"
                 : "=r"(r0), "=r"(r1), "=r"(r2), "=r"(r3) : "r"(addr));
}
__device__ __forceinline__ void ldsm_x2(unsigned& r0, unsigned& r1, unsigned addr) {
    asm volatile("ldmatrix.sync.aligned.m8n8.x2.shared.b16 {%0,%1}, [%2];"
                 : "=r"(r0), "=r"(r1) : "r"(addr));
}
__device__ __forceinline__ void mma16816(float* d,
                                         unsigned a0, unsigned a1, unsigned a2, unsigned a3,
                                         unsigned b0, unsigned b1) {
    asm volatile("mma.sync.aligned.m16n8k16.row.col.f32.bf16.bf16.f32 "
                 "{%0,%1,%2,%3}, {%4,%5,%6,%7}, {%8,%9}, {%0,%1,%2,%3};"
                 : "+f"(d[0]), "+f"(d[1]), "+f"(d[2]), "+f"(d[3])
                 : "r"(a0), "r"(a1), "r"(a2), "r"(a3), "r"(b0), "r"(b1));
}

// ---------------------------------------------------------------------------
// K0a: Wx -> bf16 transposed [n][k], k padded to 120 with zeros
// ---------------------------------------------------------------------------
__global__ void k0_wx(const float* __restrict__ Wx)
{
    int n = blockIdx.x;
    for (int k = threadIdx.x; k < 120; k += 128)
        g_WxT[n * 120 + k] = (k < EMB)
            ? (unsigned short)__bfloat16_as_ushort(__float2bfloat16(Wx[(size_t)k * GATES + n]))
            : (unsigned short)0;
}
// K0b: emb -> bf16
__global__ void k0_emb(const float* __restrict__ emb)
{
    for (size_t i = blockIdx.x * blockDim.x + threadIdx.x;
         i < (size_t)VOCAB * EMB; i += (size_t)gridDim.x * blockDim.x)
        g_embh[i] = (unsigned short)__bfloat16_as_ushort(__float2bfloat16(emb[i]));
}

// ---------------------------------------------------------------------------
// K1 (v6): PERSISTENT embedding gather + input projection via bf16 mma
//   grid (296, 2) = 2 CTAs/SM. Each CTA stages its 256-col half of WxT ONCE
//   (61 KB), then loops over row-tiles (64 rows each): gather A -> mma ->
//   fragments -> zb -> coalesced stores. zb has its own smem region (Bs
//   persists across tiles). Bias accumulator-init hoisted to registers.
// ---------------------------------------------------------------------------
#define K1_ROWS  64
#define K1_COLSB 256
#define K1_KPAD  112
#define K1_KSTR  120   // smem row stride in bf16 elems (240 B)
#define K1_GRIDX 296
#define K1_TILES (BATCH * SEQ / K1_ROWS)               // 4000
#define K1_BS_BYTES (K1_COLSB * K1_KSTR * 2)           // 61440
#define K1_AS_BYTES (K1_ROWS * K1_KSTR * 2)            // 15360
#define ZB_STR   264   // bf16 elems per zb row (528 B)
#define K1_ZB_BYTES (K1_ROWS * ZB_STR * 2)             // 33792
#define K1_SMEM  (K1_BS_BYTES + K1_AS_BYTES + K1_ZB_BYTES)  // 110592

__global__ __launch_bounds__(256) void k1_embed_proj(
    const int* __restrict__ tokens, const float* __restrict__ bias)
{
    extern __shared__ __align__(16) unsigned char k1sm[];
    unsigned short (*Bs)[K1_KSTR] = (unsigned short (*)[K1_KSTR])k1sm;
    unsigned short (*As)[K1_KSTR] =
        (unsigned short (*)[K1_KSTR])(k1sm + K1_BS_BYTES);
    __nv_bfloat16 (*zb)[ZB_STR] =
        (__nv_bfloat16 (*)[ZB_STR])(k1sm + K1_BS_BYTES + K1_AS_BYTES);

    const int tid  = threadIdx.x;
    const int c0   = blockIdx.y * K1_COLSB;
    const int wid  = tid >> 5;
    const int lane = tid & 31;
    const int rw   = wid & 3;     // row-warp: rows rw*16..+15
    const int cw   = wid >> 2;    // col-warp: cols cw*128..+127
    const int frow = lane >> 2;

    // ---- stage B ONCE: memcpy pre-transposed WxT rows (15 uint4 per row) ----
    for (int idx = tid; idx < K1_COLSB * 15; idx += 256) {
        int n = idx / 15, q = idx - n * 15;
        *(uint4*)&Bs[n][q * 8] =
            *(const uint4*)&g_WxT[(size_t)(c0 + n) * K1_KSTR + q * 8];
    }
    // ---- zero As K-tail once (gather never touches k >= 100) ----
    for (int idx = tid; idx < K1_ROWS * 5; idx += 256) {
        int r = idx / 5, j = idx - r * 5;
        *(uint2*)&As[r][EMB + 4 * j] = make_uint2(0u, 0u);
    }

    // ---- hoisted bias accumulator seeds ----
    float2 bj[16];
    #pragma unroll
    for (int j = 0; j < 16; j++)
        bj[j] = *(const float2*)&bias[c0 + cw * 128 + j * 8 + (lane & 3) * 2];

    unsigned a_base = (unsigned)__cvta_generic_to_shared(
                          &As[rw * 16 + (lane & 15)][0]) + ((lane >> 4) * 8) * 2;
    unsigned b_base = (unsigned)__cvta_generic_to_shared(
                          &Bs[cw * 128 + (lane & 7)][0]) + (((lane >> 3) & 1) * 8) * 2;
    __syncthreads();   // Bs + As-tail ready

    for (int tile = blockIdx.x; tile < K1_TILES; tile += K1_GRIDX) {
        const int row0 = tile * K1_ROWS;

        // ---- gather A: bf16 emb rows, 25 uint2 per row (token LDG direct) ----
        for (int idx = tid; idx < K1_ROWS * 25; idx += 256) {
            int r = idx / 25, q = idx - r * 25;
            int tok = tokens[row0 + r];          // L1-cached broadcast
            *(uint2*)&As[r][q * 4] =
                *(const uint2*)&g_embh[(size_t)tok * EMB + q * 4];
        }
        __syncthreads();   // As ready (also: prev tile's zb reads drained)

        // ---- mma ----
        float acc[16][4];
        #pragma unroll
        for (int j = 0; j < 16; j++) {
            acc[j][0] = bj[j].x; acc[j][1] = bj[j].y;
            acc[j][2] = bj[j].x; acc[j][3] = bj[j].y;
        }
        #pragma unroll
        for (int k = 0; k < K1_KPAD / 16; k++) {
            unsigned a0, a1, a2, a3;
            ldsm_x4(a0, a1, a2, a3, a_base + k * 32);
            #pragma unroll
            for (int j = 0; j < 16; j++) {
                unsigned b0, b1;
                ldsm_x2(b0, b1, b_base + j * (8 * K1_KSTR * 2) + k * 32);
                mma16816(acc[j], a0, a1, a2, a3, b0, b1);
            }
        }
        __syncthreads();   // all warps done reading As; zb free

        // ---- fragments -> zb (conflict-free) ----
        {
            int r_lo = rw * 16 + frow;
            int colb = cw * 128 + (lane & 3) * 2;
            #pragma unroll
            for (int j = 0; j < 16; j++) {
                int col = colb + j * 8;
                *(__nv_bfloat162*)&zb[r_lo][col] =
                    __floats2bfloat162_rn(acc[j][0], acc[j][1]);
                *(__nv_bfloat162*)&zb[r_lo + 8][col] =
                    __floats2bfloat162_rn(acc[j][2], acc[j][3]);
            }
        }
        __syncthreads();

        // ---- coalesced store: 512B per row ----
        for (int idx = tid; idx < K1_ROWS * 32; idx += 256) {
            int row = idx >> 5, ch = idx & 31;
            int gr = row0 + row;
            int b  = gr / SEQ;
            int t  = gr - b * SEQ;
            size_t off = ((size_t)t * BATCH + b) * GATES + c0 + ch * 8;
            uint4 v = *(uint4*)&zb[row][ch * 8];
            __stcs((uint4*)&g_xz[off], v);
        }
        // loop back: gather overwrites As (safe: mma reads barriered);
        // zb overwrite is behind two barriers of the next tile.
    }
}

// ---------------------------------------------------------------------------
// K2 (v9, R15 winner verbatim): tensor-core LSTM recurrence, gate-aligned.
// ---------------------------------------------------------------------------
#define K2_THREADS 512
#define HS_STR   136
#define HSBUF_BYTES (16 * HS_STR * 2)                  // 4352 per buffer
#define SM_HS_BYTES (2 * HSBUF_BYTES)                  // 8704
#define SM_BST_BYTES (128 * HS_STR * 2)                // 34816 (setup overlay)
#define SM_TOTAL (SM_HS_BYTES + SM_BST_BYTES)          // 43520

__device__ __forceinline__ float tanh_fast(float x) {
    float r;
    asm("tanh.approx.f32 %0, %1;" : "=f"(r) : "f"(x));
    return r;
}
__device__ __forceinline__ float sigm_fast(float x) {
    return fmaf(0.5f, tanh_fast(0.5f * x), 0.5f);
}

__global__ __launch_bounds__(K2_THREADS, 1) void k2_lstm_head(
    const float* __restrict__ Wh,
    const float* __restrict__ W1, const float* __restrict__ b1,
    const float* __restrict__ W2, const float* __restrict__ b2,
    float* __restrict__ out)
{
    __shared__ __align__(16) unsigned char sm[SM_TOTAL];
    unsigned short (*hs0)[HS_STR] = (unsigned short (*)[HS_STR])sm;  // 2 buffers
    unsigned short (*BsT)[HS_STR] =
        (unsigned short (*)[HS_STR])(sm + SM_HS_BYTES);              // setup overlay
    float (*d1s)[DENSE] = (float (*)[DENSE])(sm + SM_HS_BYTES);      // post-loop overlay

    const int tid  = threadIdx.x;
    const int warp = tid >> 5;
    const int lane = tid & 31;
    const int b0   = blockIdx.x * 8;
    const int frow = lane >> 2;

    // ---- one-time: register-resident B fragments of Wh, gate-aligned ----
    unsigned breg[8][4][2];
    #pragma unroll 1
    for (int p = 0; p < 4; p++) {
        for (int idx = tid; idx < 128 * 128; idx += K2_THREADS) {
            int n = idx & 127, k = idx >> 7;
            BsT[n][k] = (unsigned short)__bfloat16_as_ushort(
                __float2bfloat16(Wh[(size_t)k * GATES + p * 128 + n]));
        }
        __syncthreads();
        {
            unsigned b_base = (unsigned)__cvta_generic_to_shared(
                &BsT[warp * 8 + (lane & 7)][0]) + (((lane >> 3) & 1) * 8) * 2;
            #pragma unroll
            for (int kk = 0; kk < 8; kk++)
                ldsm_x2(breg[kk][p][0], breg[kk][p][1], b_base + kk * 32);
        }
        __syncthreads();
    }

    // ---- init h buffers = 0 ----
    for (int i = tid; i < 2 * 16 * HS_STR; i += K2_THREADS)
        ((unsigned short*)sm)[i] = 0;
    float c[2] = {0.0f, 0.0f};
    __syncthreads();

    unsigned a_base0 = (unsigned)__cvta_generic_to_shared(
        &hs0[lane & 15][(lane >> 4) * 8]);

    const unsigned short* xzp =
        &g_xz[((size_t)b0 + frow) * GATES + warp * 8 + (lane & 3) * 2];
    unsigned xcur[4];
    #pragma unroll
    for (int j = 0; j < 4; j++)
        xcur[j] = __ldcs((const unsigned*)&xzp[j * UNITS]);

    int cur = 0;
    const int u0 = warp * 8 + (lane & 3) * 2;
    for (int t = 0; t < SEQ; t++) {
        float d[4][4];
        #pragma unroll
        for (int j = 0; j < 4; j++) {
            d[j][0] = bf2f((unsigned short)(xcur[j] & 0xFFFF));
            d[j][1] = bf2f((unsigned short)(xcur[j] >> 16));
            d[j][2] = 0.0f; d[j][3] = 0.0f;
        }
        if (t + 1 < SEQ) {
            xzp += (size_t)BATCH * GATES;
            #pragma unroll
            for (int j = 0; j < 4; j++)
                xcur[j] = __ldcs((const unsigned*)&xzp[j * UNITS]);
        }

        unsigned a_base = a_base0 + cur * HSBUF_BYTES;
        #pragma unroll
        for (int kk = 0; kk < 8; kk++) {
            unsigned a0, a1, a2, a3;
            ldsm_x4(a0, a1, a2, a3, a_base + kk * 32);
            #pragma unroll
            for (int j = 0; j < 4; j++)
                mma16816(d[j], a0, a1, a2, a3, breg[kk][j][0], breg[kk][j][1]);
        }

        float hv[2];
        #pragma unroll
        for (int h = 0; h < 2; h++) {
            float ig = sigm_fast(d[0][h]);
            float fg = sigm_fast(d[1][h]);
            float gg = tanh_fast(d[2][h]);
            float og = sigm_fast(d[3][h]);
            float cc = fg * c[h] + ig * gg;
            c[h] = cc;
            hv[h] = og * tanh_fast(cc);
        }
        *(__nv_bfloat162*)&hs0[(cur ^ 1) * 16 + frow][u0] =
            __floats2bfloat162_rn(hv[0], hv[1]);
        __syncthreads();
        cur ^= 1;
    }

    // ---- dense head: relu(h @ W1 + b1) @ W2 + b2, softmax ----
    const unsigned short (*hf)[HS_STR] = &hs0[cur * 16];
    if (tid < 256) {
        int r = tid >> 5;
        int j = tid & 31;
        float a = b1[j];
        #pragma unroll 8
        for (int k = 0; k < UNITS; k++)
            a += bf2f(hf[r][k]) * W1[k * DENSE + j];
        d1s[r][j] = fmaxf(a, 0.0f);
    }
    __syncthreads();
    if (tid < 8) {
        float l0 = b2[0], l1 = b2[1];
        #pragma unroll
        for (int j = 0; j < DENSE; j++) {
            float d = d1s[tid][j];
            l0 += d * W2[j * 2 + 0];
            l1 += d * W2[j * 2 + 1];
        }
        float m  = fmaxf(l0, l1);
        float e0 = __expf(l0 - m), e1 = __expf(l1 - m);
        float s  = __fdividef(1.0f, e0 + e1);
        out[(b0 + tid) * 2 + 0] = e0 * s;
        out[(b0 + tid) * 2 + 1] = e1 * s;
    }
}

// ---------------------------------------------------------------------------
extern "C" void kernel_launch(void* const* d_in, const int* in_sizes, int n_in,
                              void* d_out, int out_size)
{
    const int*   tokens = (const int*)  d_in[0];
    const float* emb    = (const float*)d_in[1];
    const float* Wx     = (const float*)d_in[2];
    const float* Wh     = (const float*)d_in[3];
    const float* lb     = (const float*)d_in[4];
    const float* W1     = (const float*)d_in[5];
    const float* b1     = (const float*)d_in[6];
    const float* W2     = (const float*)d_in[7];
    const float* b2     = (const float*)d_in[8];
    float* out = (float*)d_out;

    cudaFuncSetAttribute(k1_embed_proj,
                         cudaFuncAttributeMaxDynamicSharedMemorySize, K1_SMEM);

    k0_wx<<<GATES, 128>>>(Wx);
    k0_emb<<<2048, 256>>>(emb);
    dim3 g1(K1_GRIDX, GATES / K1_COLSB);   // (296, 2)
    k1_embed_proj<<<g1, 256, K1_SMEM>>>(tokens, lb);
    k2_lstm_head<<<BATCH / 8, K2_THREADS>>>(Wh, W1, b1, W2, b2, out);
}